// round 5
// baseline (speedup 1.0000x reference)
#include <cuda_runtime.h>
#include <math.h>

#define NS 8192
#define NT 8192
#define NC 91
#define NO_OBJ 90
#define NBC 32                 // cells per dimension
#define NCELL (NBC * NBC)      // 1024
#define RWIN 4                 // cell halo: |dcell| <= 4 (box extent <= 105px, cell 31.25px)
#define ROW_BLOCKS (NS / 8)
#define IOU_BLOCKS (NCELL / 8)

// ---------------- scratch (static __device__, no allocations) ----------------
__device__ unsigned int g_hist[2 * NCELL];   // [cell]=students, [NCELL+cell]=teachers
__device__ unsigned int g_cur[2 * NCELL];    // scatter cursors
__device__ int g_sstart[NCELL + 1];
__device__ int g_tstart[NCELL + 1];
__device__ float4 g_sbox[NS];                // sorted (x1,y1,x2+1,y2+1)
__device__ int    g_sidx[NS];
__device__ float4 g_tbox[NT];
__device__ float2 g_tmeta[NT];               // (area, idx_bits)
__device__ float4 g_best[NS];                // per ORIGINAL student: (u, d, idx_bits, 0)
__device__ float g_bpart[ROW_BLOCKS * 3];
__device__ unsigned int g_count = 0;

__device__ __forceinline__ int cell_of(float x, float y) {
    int cx = min(max((int)(x * (NBC / 1000.0f)), 0), NBC - 1);
    int cy = min(max((int)(y * (NBC / 1000.0f)), 0), NBC - 1);
    return (cx << 5) + cy;                   // x-major, y minor (y-window contiguous)
}

__device__ __forceinline__ unsigned int wscan(unsigned int x, int lane) {
#pragma unroll
    for (int o = 1; o < 32; o <<= 1) {
        unsigned int y = __shfl_up_sync(0xffffffffu, x, o);
        if (lane >= o) x += y;
    }
    return x;
}

// ---------------- kernel 1: 2D-cell histogram ----------------
__global__ void __launch_bounds__(256) hist_kernel(const float* __restrict__ bs,
                                                   const float* __restrict__ bt) {
    int i = blockIdx.x * 256 + threadIdx.x;   // 32 blocks * 256 = 8192
    float4 s = ((const float4*)bs)[i];
    atomicAdd(&g_hist[cell_of(s.x, s.y)], 1u);
    float4 t = ((const float4*)bt)[i];
    atomicAdd(&g_hist[NCELL + cell_of(t.x, t.y)], 1u);
}

// ---------------- kernel 2: scan both 1024-bin histograms ----------------
__global__ void __launch_bounds__(1024) scan_kernel() {
    __shared__ unsigned int ws0[32], ws1[32];
    int tid = threadIdx.x, lane = tid & 31, w = tid >> 5;

    unsigned int vs = g_hist[tid];
    unsigned int vt = g_hist[NCELL + tid];
    unsigned int xs = wscan(vs, lane);
    unsigned int xt = wscan(vt, lane);
    if (lane == 31) { ws0[w] = xs; ws1[w] = xt; }
    __syncthreads();
    if (w == 0) {
        unsigned int a = ws0[lane], b = ws1[lane];
        unsigned int sa = wscan(a, lane), sb = wscan(b, lane);
        ws0[lane] = sa - a;                  // exclusive warp-sum prefix
        ws1[lane] = sb - b;
    }
    __syncthreads();
    unsigned int es = xs - vs + ws0[w];
    unsigned int et = xt - vt + ws1[w];
    g_sstart[tid] = (int)es;
    g_tstart[tid] = (int)et;
    g_cur[tid] = es;
    g_cur[NCELL + tid] = et;
    if (tid == 0) { g_sstart[NCELL] = NS; g_tstart[NCELL] = NT; }
    g_hist[tid] = 0;                         // self-reset for graph replay
    g_hist[NCELL + tid] = 0;
}

// ---------------- kernel 3: scatter into cell order ----------------
__global__ void __launch_bounds__(256) scatter_kernel(const float* __restrict__ bs,
                                                      const float* __restrict__ bt) {
    int i = blockIdx.x * 256 + threadIdx.x;
    {
        float4 r = ((const float4*)bs)[i];
        unsigned int pos = atomicAdd(&g_cur[cell_of(r.x, r.y)], 1u);
        g_sbox[pos] = make_float4(r.x, r.y, r.z + 1.0f, r.w + 1.0f);
        g_sidx[pos] = i;
    }
    {
        float4 r = ((const float4*)bt)[i];
        unsigned int pos = atomicAdd(&g_cur[NCELL + cell_of(r.x, r.y)], 1u);
        float x2 = r.z + 1.0f, y2 = r.w + 1.0f;
        g_tbox[pos] = make_float4(r.x, r.y, x2, y2);
        g_tmeta[pos] = make_float2((x2 - r.x) * (y2 - r.y), __int_as_float(i));
    }
}

// ---------------- kernel 4: windowed IoU argmax (warp per student cell) -----
__global__ void __launch_bounds__(256) iou_kernel() {
    int tid = threadIdx.x, wid = tid >> 5, lane = tid & 31;
    int cid = blockIdx.x * 8 + wid;

    int sst = g_sstart[cid];
    int cnt = g_sstart[cid + 1] - sst;
    if (cnt == 0) return;

    int cx = cid >> 5, cy = cid & 31;
    int txlo = max(cx - RWIN, 0), txhi = min(cx + RWIN, NBC - 1);
    int tylo = max(cy - RWIN, 0), tyhi = min(cy + RWIN, NBC - 1);
    int s_local = lane >> 1, t_off = lane & 1;

    for (int sb = 0; sb < cnt; sb += 16) {
        int si = sb + s_local;
        bool act = si < cnt;
        int p = sst + (act ? si : 0);
        float4 sbx = g_sbox[p];
        float sA = (sbx.z - sbx.x) * (sbx.w - sbx.y);

        float u0 = 0.0f, d0 = 1.0f; int i0 = 0x7fffffff;   // chain A
        float u1 = 0.0f, d1 = 1.0f; int i1 = 0x7fffffff;   // chain B

        for (int tx = txlo; tx <= txhi; tx++) {
            int lo = g_tstart[(tx << 5) + tylo];
            int hi = g_tstart[(tx << 5) + tyhi + 1];
            int j = lo + t_off;
            for (; j + 2 < hi; j += 4) {
                {
                    float4 t = g_tbox[j];
                    float2 m = g_tmeta[j];
                    float w = fminf(sbx.z, t.z) - fmaxf(sbx.x, t.x);
                    float h = fminf(sbx.w, t.w) - fmaxf(sbx.y, t.y);
                    w = fmaxf(w, 0.0f);          // h unclamped: u<=0 never wins
                    float u = w * h;
                    float dd = sA + m.x;
                    if (u * d0 > u0 * dd) { u0 = u; d0 = dd; i0 = __float_as_int(m.y); }
                }
                {
                    float4 t = g_tbox[j + 2];
                    float2 m = g_tmeta[j + 2];
                    float w = fminf(sbx.z, t.z) - fmaxf(sbx.x, t.x);
                    float h = fminf(sbx.w, t.w) - fmaxf(sbx.y, t.y);
                    w = fmaxf(w, 0.0f);
                    float u = w * h;
                    float dd = sA + m.x;
                    if (u * d1 > u1 * dd) { u1 = u; d1 = dd; i1 = __float_as_int(m.y); }
                }
            }
            if (j < hi) {
                float4 t = g_tbox[j];
                float2 m = g_tmeta[j];
                float w = fminf(sbx.z, t.z) - fmaxf(sbx.x, t.x);
                float h = fminf(sbx.w, t.w) - fmaxf(sbx.y, t.y);
                w = fmaxf(w, 0.0f);
                float u = w * h;
                float dd = sA + m.x;
                if (u * d0 > u0 * dd) { u0 = u; d0 = dd; i0 = __float_as_int(m.y); }
            }
        }

        // merge chain B into A (exact cross-mult, min-idx tie = argmax-first)
        {
            float l = u1 * d0, r = u0 * d1;
            if (l > r || (l == r && i1 < i0)) { u0 = u1; d0 = d1; i0 = i1; }
        }
        // merge partner lane (pairs are lane-aligned)
        {
            float uo = __shfl_down_sync(0xffffffffu, u0, 1);
            float dd = __shfl_down_sync(0xffffffffu, d0, 1);
            int   io = __shfl_down_sync(0xffffffffu, i0, 1);
            float l = uo * d0, r = u0 * dd;
            if (l > r || (l == r && io < i0)) { u0 = uo; d0 = dd; i0 = io; }
        }
        if (act && t_off == 0)
            g_best[g_sidx[p]] = make_float4(u0, d0, __int_as_float(i0), 0.0f);
    }
}

// ---------------- kernel 5: row loss + deterministic final reduce ----------
__global__ void __launch_bounds__(256) row_kernel(const float* __restrict__ ps,
                                                  const float* __restrict__ pt,
                                                  float* __restrict__ out) {
    __shared__ float s_a[8], s_b[8], s_f[8];
    __shared__ bool  isLast;

    int tid  = threadIdx.x;
    int wid  = tid >> 5;
    int lane = tid & 31;
    int s = blockIdx.x * 8 + wid;          // original student id

    float4 B = g_best[s];                  // broadcast load
    float u = B.x, d = B.y;
    int idx = __float_as_int(B.z);

    float iou = u / (d - u);               // exact reference form
    bool above = iou > 0.75f;

    float a_val = 0.0f, b_val = 0.0f, f_val = 0.0f;
    if (above) {
        const float* ptr = pt + (size_t)idx * NC;
        const float* psr = ps + (size_t)s * NC;
        float acc = 0.0f;
        for (int c = lane; c < NC; c += 32) {
            float p = ptr[c];
            float q = psr[c];
            if (p > 0.0f) acc += p * (__logf(p) - __logf(q));
        }
#pragma unroll
        for (int o = 16; o > 0; o >>= 1)
            acc += __shfl_xor_sync(0xffffffffu, acc, o);
        a_val = acc;
        f_val = 1.0f;
    } else {
        if (lane == 0) b_val = -__logf(ps[(size_t)s * NC + NO_OBJ]);
    }

    if (lane == 0) { s_a[wid] = a_val; s_b[wid] = b_val; s_f[wid] = f_val; }
    __syncthreads();

    if (tid == 0) {
        float a = 0.0f, b = 0.0f, f = 0.0f;
#pragma unroll
        for (int w = 0; w < 8; w++) { a += s_a[w]; b += s_b[w]; f += s_f[w]; }
        g_bpart[blockIdx.x * 3 + 0] = a;
        g_bpart[blockIdx.x * 3 + 1] = b;
        g_bpart[blockIdx.x * 3 + 2] = f;
        __threadfence();
        unsigned int old = atomicAdd(&g_count, 1u);
        isLast = (old == (unsigned)(gridDim.x - 1));
    }
    __syncthreads();

    if (isLast) {
        __shared__ float ra[256], rb[256], rf[256];
        float a = 0.0f, b = 0.0f, f = 0.0f;
        for (int i = tid; i < ROW_BLOCKS; i += 256) {
            a += g_bpart[i * 3 + 0];
            b += g_bpart[i * 3 + 1];
            f += g_bpart[i * 3 + 2];
        }
        ra[tid] = a; rb[tid] = b; rf[tid] = f;
        __syncthreads();
        for (int o = 128; o > 0; o >>= 1) {
            if (tid < o) {
                ra[tid] += ra[tid + o];
                rb[tid] += rb[tid + o];
                rf[tid] += rf[tid + o];
            }
            __syncthreads();
        }
        if (tid == 0) {
            float na = rf[0];
            float nb = (float)NS - na;
            float at = (na > 0.0f) ? ra[0] / (na * (float)NC) : 0.0f;
            float bt = (nb > 0.0f) ? rb[0] / (nb * (float)NC) : 0.0f;
            out[0] = at + bt;
            g_count = 0;                   // self-reset for graph replay
        }
    }
}

// ---------------- launcher ----------------
extern "C" void kernel_launch(void* const* d_in, const int* in_sizes, int n_in,
                              void* d_out, int out_size) {
    const float* boxes_student = (const float*)d_in[0];
    const float* boxes_teacher = (const float*)d_in[1];
    const float* pred_student  = (const float*)d_in[2];
    const float* pred_teacher  = (const float*)d_in[3];
    float* out = (float*)d_out;

    hist_kernel<<<32, 256>>>(boxes_student, boxes_teacher);
    scan_kernel<<<1, 1024>>>();
    scatter_kernel<<<32, 256>>>(boxes_student, boxes_teacher);
    iou_kernel<<<IOU_BLOCKS, 256>>>();
    row_kernel<<<ROW_BLOCKS, 256>>>(pred_student, pred_teacher, out);
}

// round 6
// speedup vs baseline: 2.4046x; 2.4046x over previous
#include <cuda_runtime.h>
#include <math.h>

#define NS 8192
#define NT 8192
#define NC 91
#define NO_OBJ 90

#define SXB 32                  // student x bins
#define TXB 64                  // teacher x bins
#define YB  64                  // y bins (both)
#define NSCELL (SXB * YB)       // 2048
#define NTCELL (TXB * YB)       // 4096
#define SBLK (NS / 256)         // 32 student blocks
#define ROW_BLOCKS (NS / 8)     // 1024

// ---------------- scratch (static __device__, no allocations) ----------------
__device__ unsigned int g_hist[NSCELL + NTCELL];
__device__ unsigned int g_cur[NSCELL + NTCELL];
__device__ int g_sstart[NSCELL + 1];
__device__ int g_tstart[NTCELL + 1];
__device__ float4 g_sbox[NS];          // sorted (x1,y1,x2+1,y2+1)
__device__ int    g_sidx[NS];
__device__ float4 g_tbox[NT];
__device__ float2 g_tmeta[NT];         // (area, idx_bits)
__device__ float4 g_part[NS * TXB];    // [sorted_s*64 + tx]; only live entries written
__device__ float g_bpart[ROW_BLOCKS * 3];
__device__ unsigned int g_count = 0;

__device__ __forceinline__ int bin_sx(float x) {
    return min(max((int)(x * (SXB / 1000.0f)), 0), SXB - 1);
}
__device__ __forceinline__ int bin_tx(float x) {
    return min(max((int)(x * (TXB / 1000.0f)), 0), TXB - 1);
}
__device__ __forceinline__ int bin_y(float y) {
    return min(max((int)(y * (YB / 1000.0f)), 0), YB - 1);
}

__device__ __forceinline__ unsigned int wscan(unsigned int x, int lane) {
#pragma unroll
    for (int o = 1; o < 32; o <<= 1) {
        unsigned int y = __shfl_up_sync(0xffffffffu, x, o);
        if (lane >= o) x += y;
    }
    return x;
}

// Exact integer prune bounds, units of 1/32 px, +-1 slack for float-bin rounding.
// Same integer arithmetic in iou_kernel and row_kernel -> identical decisions.
__device__ __forceinline__ void block_xbounds(int sb, int& BXLO, int& BXHI) {
    int b0 = bin_sx(g_sbox[sb * 256].x);
    int b1 = bin_sx(g_sbox[sb * 256 + 255].x);
    BXLO = b0 * 1000 - 1;                  // 31.25px * 32 = 1000
    BXHI = (b1 + 1) * 1000 + 3361;         // + maxExtent 105px*32 + slack
}
__device__ __forceinline__ bool tx_live(int tx, int BXLO, int BXHI) {
    int TXLO = tx * 500 - 1;               // 15.625px * 32 = 500
    int TXHI = (tx + 1) * 500 + 3361;
    return !(TXLO >= BXHI || TXHI <= BXLO);
}

// ---------------- kernel 1: 2D histograms ----------------
__global__ void __launch_bounds__(256) hist_kernel(const float* __restrict__ bs,
                                                   const float* __restrict__ bt) {
    int i = blockIdx.x * 256 + threadIdx.x;
    float4 s = ((const float4*)bs)[i];
    atomicAdd(&g_hist[bin_sx(s.x) * YB + bin_y(s.y)], 1u);
    float4 t = ((const float4*)bt)[i];
    atomicAdd(&g_hist[NSCELL + bin_tx(t.x) * YB + bin_y(t.y)], 1u);
}

// ---------------- kernel 2: scan both histograms (self-zeroing) ----------------
__global__ void __launch_bounds__(1024) scan_kernel() {
    __shared__ unsigned int ws[32];
    int tid = threadIdx.x, lane = tid & 31, w = tid >> 5;

    // students: 2 contiguous bins per thread
    {
        unsigned int v0 = g_hist[2 * tid], v1 = g_hist[2 * tid + 1];
        unsigned int tot = v0 + v1;
        unsigned int x = wscan(tot, lane);
        if (lane == 31) ws[w] = x;
        __syncthreads();
        if (w == 0) { unsigned int a = ws[lane]; unsigned int sa = wscan(a, lane); ws[lane] = sa - a; }
        __syncthreads();
        unsigned int base = x - tot + ws[w];
        g_sstart[2 * tid] = (int)base;
        g_sstart[2 * tid + 1] = (int)(base + v0);
        g_cur[2 * tid] = base;
        g_cur[2 * tid + 1] = base + v0;
        g_hist[2 * tid] = 0; g_hist[2 * tid + 1] = 0;
        if (tid == 0) g_sstart[NSCELL] = NS;
        __syncthreads();
    }
    // teachers: 4 contiguous bins per thread
    {
        unsigned int v[4]; unsigned int tot = 0;
#pragma unroll
        for (int k = 0; k < 4; k++) { v[k] = g_hist[NSCELL + 4 * tid + k]; tot += v[k]; }
        unsigned int x = wscan(tot, lane);
        if (lane == 31) ws[w] = x;
        __syncthreads();
        if (w == 0) { unsigned int a = ws[lane]; unsigned int sa = wscan(a, lane); ws[lane] = sa - a; }
        __syncthreads();
        unsigned int base = x - tot + ws[w];
#pragma unroll
        for (int k = 0; k < 4; k++) {
            g_tstart[4 * tid + k] = (int)base;
            g_cur[NSCELL + 4 * tid + k] = base;
            g_hist[NSCELL + 4 * tid + k] = 0;
            base += v[k];
        }
        if (tid == 0) g_tstart[NTCELL] = NT;
    }
}

// ---------------- kernel 3: scatter into 2D-cell order ----------------
__global__ void __launch_bounds__(256) scatter_kernel(const float* __restrict__ bs,
                                                      const float* __restrict__ bt) {
    int i = blockIdx.x * 256 + threadIdx.x;
    {
        float4 r = ((const float4*)bs)[i];
        unsigned int pos = atomicAdd(&g_cur[bin_sx(r.x) * YB + bin_y(r.y)], 1u);
        g_sbox[pos] = make_float4(r.x, r.y, r.z + 1.0f, r.w + 1.0f);
        g_sidx[pos] = i;
    }
    {
        float4 r = ((const float4*)bt)[i];
        unsigned int pos = atomicAdd(&g_cur[NSCELL + bin_tx(r.x) * YB + bin_y(r.y)], 1u);
        float x2 = r.z + 1.0f, y2 = r.w + 1.0f;
        g_tbox[pos] = make_float4(r.x, r.y, x2, y2);
        g_tmeta[pos] = make_float2((x2 - r.x) * (y2 - r.y), __int_as_float(i));
    }
}

#define IOU_STEP(J, U, D, I) {                                      \
    float4 t = tbs[J]; float2 m = tms[J];                           \
    float w_ = fminf(sbx.z, t.z) - fmaxf(sbx.x, t.x);               \
    float h_ = fminf(sbx.w, t.w) - fmaxf(sbx.y, t.y);               \
    w_ = fmaxf(w_, 0.0f);          /* h unclamped: u<=0 never wins */ \
    float u_ = w_ * h_;                                             \
    float dd_ = sA + m.x;                                           \
    if (u_ * (D) > (U) * dd_) { U = u_; D = dd_; I = __float_as_int(m.y); } }

// ---------------- kernel 4: pruned + y-windowed IoU argmax ----------------
__global__ void __launch_bounds__(256) iou_kernel() {
    int tid = threadIdx.x;
    int sb = blockIdx.x, tx = blockIdx.y;

    int BXLO, BXHI;
    block_xbounds(sb, BXLO, BXHI);
    if (!tx_live(tx, BXLO, BXHI)) return;     // block-uniform early exit

    __shared__ float4 tbs[256];
    __shared__ float2 tms[256];

    int p = sb * 256 + tid;
    float4 sbx = g_sbox[p];
    float sA = (sbx.z - sbx.x) * (sbx.w - sbx.y);

    // warp y-window (students y-sorted within block -> tight per warp)
    float wy0 = sbx.y, wy1 = sbx.w;
#pragma unroll
    for (int o = 16; o > 0; o >>= 1) {
        wy0 = fminf(wy0, __shfl_xor_sync(0xffffffffu, wy0, o));
        wy1 = fmaxf(wy1, __shfl_xor_sync(0xffffffffu, wy1, o));
    }
    int ylo = bin_y(wy0 - 105.0f);
    int yhi = bin_y(wy1);
    int jlo = g_tstart[(tx << 6) + ylo];       // exact bounds from bin table:
    int jhi = g_tstart[(tx << 6) + yhi + 1];   // safe regardless of within-bin order
    int tb0 = g_tstart[tx << 6];
    int tb1 = g_tstart[(tx + 1) << 6];

    float u0 = 0.0f, d0 = 1.0f; int i0 = 0x7fffffff;
    float u1 = 0.0f, d1 = 1.0f; int i1 = 0x7fffffff;

    for (int base = tb0; base < tb1; base += 256) {
        int n = min(256, tb1 - base);
        __syncthreads();
        if (tid < n) { tbs[tid] = g_tbox[base + tid]; tms[tid] = g_tmeta[base + tid]; }
        __syncthreads();
        int lo = max(jlo - base, 0), hi = min(jhi - base, n);
        int j = lo;
        for (; j + 1 < hi; j += 2) { IOU_STEP(j, u0, d0, i0); IOU_STEP(j + 1, u1, d1, i1); }
        if (j < hi) IOU_STEP(j, u0, d0, i0);
    }
    // merge chains (exact cross-mult, min-idx tie = argmax-first)
    {
        float l = u1 * d0, r = u0 * d1;
        if (l > r || (l == r && i1 < i0)) { u0 = u1; d0 = d1; i0 = i1; }
    }
    g_part[p * TXB + tx] = make_float4(u0, d0, __int_as_float(i0), 0.0f);
}

// ---------------- kernel 5: merge + row loss + deterministic final reduce ----
__global__ void __launch_bounds__(256) row_kernel(const float* __restrict__ ps,
                                                  const float* __restrict__ pt,
                                                  float* __restrict__ out) {
    __shared__ float s_a[8], s_b[8], s_f[8];
    __shared__ bool  isLast;

    int tid  = threadIdx.x;
    int wid  = tid >> 5;
    int lane = tid & 31;
    int ss = blockIdx.x * 8 + wid;        // sorted student id
    int sb = ss >> 8;

    int BXLO, BXHI;
    block_xbounds(sb, BXLO, BXHI);        // identical integer prune as iou_kernel

    float u = 0.0f, d = 1.0f; int idx = 0x7fffffff;
#pragma unroll
    for (int k = 0; k < 2; k++) {
        int tx = lane + k * 32;
        if (tx_live(tx, BXLO, BXHI)) {
            float4 P = g_part[ss * TXB + tx];
            float uu = P.x, dd = P.y; int ii = __float_as_int(P.z);
            float l = uu * d, r = u * dd;
            if (l > r || (l == r && ii < idx)) { u = uu; d = dd; idx = ii; }
        }
    }
#pragma unroll
    for (int o = 16; o > 0; o >>= 1) {
        float uo = __shfl_down_sync(0xffffffffu, u, o);
        float dd = __shfl_down_sync(0xffffffffu, d, o);
        int   io = __shfl_down_sync(0xffffffffu, idx, o);
        float l = uo * d, r = u * dd;
        if (l > r || (l == r && io < idx)) { u = uo; d = dd; idx = io; }
    }
    u   = __shfl_sync(0xffffffffu, u, 0);
    d   = __shfl_sync(0xffffffffu, d, 0);
    idx = __shfl_sync(0xffffffffu, idx, 0);

    int sorig = g_sidx[ss];

    float iou = u / (d - u);              // exact reference form
    bool above = iou > 0.75f;

    float a_val = 0.0f, b_val = 0.0f, f_val = 0.0f;
    if (above) {
        const float* ptr = pt + (size_t)idx * NC;
        const float* psr = ps + (size_t)sorig * NC;
        float acc = 0.0f;
        for (int c = lane; c < NC; c += 32) {
            float p = ptr[c];
            float q = psr[c];
            if (p > 0.0f) acc += p * (__logf(p) - __logf(q));
        }
#pragma unroll
        for (int o = 16; o > 0; o >>= 1)
            acc += __shfl_xor_sync(0xffffffffu, acc, o);
        a_val = acc;
        f_val = 1.0f;
    } else {
        if (lane == 0) b_val = -__logf(ps[(size_t)sorig * NC + NO_OBJ]);
    }

    if (lane == 0) { s_a[wid] = a_val; s_b[wid] = b_val; s_f[wid] = f_val; }
    __syncthreads();

    if (tid == 0) {
        float a = 0.0f, b = 0.0f, f = 0.0f;
#pragma unroll
        for (int w = 0; w < 8; w++) { a += s_a[w]; b += s_b[w]; f += s_f[w]; }
        g_bpart[blockIdx.x * 3 + 0] = a;
        g_bpart[blockIdx.x * 3 + 1] = b;
        g_bpart[blockIdx.x * 3 + 2] = f;
        __threadfence();
        unsigned int old = atomicAdd(&g_count, 1u);
        isLast = (old == (unsigned)(gridDim.x - 1));
    }
    __syncthreads();

    if (isLast) {
        __shared__ float ra[256], rb[256], rf[256];
        float a = 0.0f, b = 0.0f, f = 0.0f;
        for (int i = tid; i < ROW_BLOCKS; i += 256) {
            a += g_bpart[i * 3 + 0];
            b += g_bpart[i * 3 + 1];
            f += g_bpart[i * 3 + 2];
        }
        ra[tid] = a; rb[tid] = b; rf[tid] = f;
        __syncthreads();
        for (int o = 128; o > 0; o >>= 1) {
            if (tid < o) {
                ra[tid] += ra[tid + o];
                rb[tid] += rb[tid + o];
                rf[tid] += rf[tid + o];
            }
            __syncthreads();
        }
        if (tid == 0) {
            float na = rf[0];
            float nb = (float)NS - na;
            float at = (na > 0.0f) ? ra[0] / (na * (float)NC) : 0.0f;
            float bt = (nb > 0.0f) ? rb[0] / (nb * (float)NC) : 0.0f;
            out[0] = at + bt;
            g_count = 0;                  // self-reset for graph replay
        }
    }
}

// ---------------- launcher ----------------
extern "C" void kernel_launch(void* const* d_in, const int* in_sizes, int n_in,
                              void* d_out, int out_size) {
    const float* boxes_student = (const float*)d_in[0];
    const float* boxes_teacher = (const float*)d_in[1];
    const float* pred_student  = (const float*)d_in[2];
    const float* pred_teacher  = (const float*)d_in[3];
    float* out = (float*)d_out;

    hist_kernel<<<32, 256>>>(boxes_student, boxes_teacher);
    scan_kernel<<<1, 1024>>>();
    scatter_kernel<<<32, 256>>>(boxes_student, boxes_teacher);

    dim3 gA(SBLK, TXB);    // 32 x 64 = 2048 blocks; ~73% exit at the prune test
    iou_kernel<<<gA, 256>>>();

    row_kernel<<<ROW_BLOCKS, 256>>>(pred_student, pred_teacher, out);
}